// round 15
// baseline (speedup 1.0000x reference)
#include <cuda_runtime.h>
#include <math.h>
#include <stdint.h>

#define T_STEPS 512
#define BATCH   64
#define IN_DIM  256
#define HID     512
#define OUT_DIM 256
#define BH      (BATCH * HID)        // 32768
#define M_ROWS  (T_STEPS * BATCH)    // 32768

// Scratch (allocation-free rule: __device__ globals)
__device__ float g_rnn[(size_t)M_ROWS * HID];  // h history (exchange medium)

// ---- barrier state: monotonic flags + persistent epoch ----
#define SCAN_CTAS 128
#define NGROUPS   4     // batch groups
__device__ __align__(128) unsigned g_flags2[NGROUPS][32];  // one 128B line per group
__device__ unsigned g_epoch;

__device__ __forceinline__ unsigned ld_acq(const unsigned* p) {
    unsigned v;
    asm volatile("ld.acquire.gpu.u32 %0, [%1];" : "=r"(v) : "l"(p));
    return v;
}
__device__ __forceinline__ void st_rel(unsigned* p, unsigned v) {
    asm volatile("st.release.gpu.u32 [%0], %1;" :: "l"(p), "r"(v));
}

// fast tanh: rel err ~1e-6, clamped (no NaN)
__device__ __forceinline__ float tanh_fast(float x) {
    float xc = fminf(9.0f, fmaxf(-9.0f, x));
    float e  = exp2f(2.885390081777927f * xc);   // e^(2x)
    return __fdividef(e - 1.0f, e + 1.0f);
}

#define FMA2(acc, a, b) asm("fma.rn.f32x2 %0, %1, %2, %0;" : "+l"(acc) : "l"(a), "l"(b))

// -------------------- fully fused RNN (v12) --------------------
// 128 CTAs = 32 col-groups x 4 batch-groups. CTA: 16 h-cols x 16 batches.
// 512 threads. Per step, inside the barrier shadow:
//   - y[t-1] GEMM (quarter-k per thread)            [R12 mechanism]
//   - xp[t+1] = x[t+1]@W_ih^T + biases (half-k)     [K1 fused away]
// h-compute is k-split across thread pairs          [R14 mechanism]
// h[t] exchanged through L2 with coalesced staging; flag barrier per bh group.
#define COLS_PER_CTA 16
#define BPC          16
#define OC_CTA       8            // y-cols per col-group (256/32)
#define WS           516
#define HS           520
#define XS           260          // x / W_ih row stride (256 + pad)
#define SW_F   (COLS_PER_CTA * WS)   // 8256 floats
#define SWO_F  (OC_CTA * WS)         // 4128
#define SWI_F  (COLS_PER_CTA * XS)   // 4160
#define SH_F   (BPC * HS)            // 8320
#define SX_F   (BPC * XS)            // 4160
#define SP_F   256                   // h partials (kh=1)
#define SP2_F  256                   // xp partials (kh=1)
#define SY_F   384                   // y partials (q=1..3)
#define SMEM_SCAN_BYTES ((SW_F + SWO_F + SWI_F + SH_F + SX_F + SP_F + SP2_F + SY_F) * 4)

__global__ __launch_bounds__(512)
void rnn_scan12(const float* __restrict__ Whh,    // [HID, HID]
                const float* __restrict__ Wih,    // [HID, IN_DIM]
                const float* __restrict__ b_ih,   // [HID]
                const float* __restrict__ b_hh,   // [HID]
                const float* __restrict__ Wout,   // [OUT_DIM, HID]
                const float* __restrict__ b_out,  // [OUT_DIM]
                const float* __restrict__ x,      // [T, B, IN_DIM]
                float* __restrict__ y,            // [T, B, O] (d_out)
                float* __restrict__ h_out)        // [B, HID]  (d_out tail)
{
    extern __shared__ float sm[];
    float* sW   = sm;                 // [16][WS]   W_hh rows
    float* sWo  = sW + SW_F;          // [8][WS]    W_out rows
    float* sWi  = sWo + SWO_F;        // [16][XS]   W_ih rows
    float* sH   = sWi + SWI_F;        // [16][HS]   h[t-1] staged
    float* sX   = sH + SH_F;          // [16][XS]   x tile (x[t+1] during step t)
    float* sP   = sX + SX_F;          // [256] h partials
    float* sP2  = sP + SP_F;          // [256] xp partials
    float* sY   = sP2 + SP2_F;        // [384] y partials
    __shared__ unsigned s_base;

    const int tid = threadIdx.x;
    const int bid = blockIdx.x;
    const int bh  = bid & 3;
    const int cg  = bid >> 2;

    // h / xp mapping: inner = tid&255 (R4 warp shape); kh = tid>>8 = k-half
    const int inner = tid & 255;
    const int kh    = tid >> 8;                   // 0 or 1
    const int w = inner >> 5, l = inner & 31;
    const int c  = ((w & 1) << 3) + (l & 7);      // 0..15
    const int bl = ((w >> 1) << 2) + (l >> 3);    // 0..15
    const int colg = cg * COLS_PER_CTA + c;
    const int b    = bh * BPC + bl;
    const int b0   = bh * BPC;

    // y mapping: o = tid&127 -> (yb, oc); q = tid>>7 = k-quarter
    const int o   = tid & 127;
    const int q   = tid >> 7;                     // 0..3
    const int yb  = o >> 3;
    const int oc  = o & 7;
    const int ocg = cg * OC_CTA + oc;
    const float bo = b_out[ocg];
    const float bias_c = b_ih[colg] + b_hh[colg];

    if (tid == 0) s_base = *(volatile unsigned*)&g_epoch;

    // cache W_hh rows [cg*16,+16), W_out rows [cg*8,+8), W_ih rows [cg*16,+16)
    for (int i = tid; i < COLS_PER_CTA * (HID / 4); i += 512) {
        int r  = i >> 7;
        int k4 = i & 127;
        float4 v = *(const float4*)&Whh[(size_t)(cg * COLS_PER_CTA + r) * HID + k4 * 4];
        *(float4*)&sW[r * WS + k4 * 4] = v;
    }
    for (int i = tid; i < OC_CTA * (HID / 4); i += 512) {
        int r  = i >> 7;
        int k4 = i & 127;
        float4 v = *(const float4*)&Wout[(size_t)(cg * OC_CTA + r) * HID + k4 * 4];
        *(float4*)&sWo[r * WS + k4 * 4] = v;
    }
    for (int i = tid; i < COLS_PER_CTA * (IN_DIM / 4); i += 512) {
        int r  = i >> 6;
        int k4 = i & 63;
        float4 v = *(const float4*)&Wih[(size_t)(cg * COLS_PER_CTA + r) * IN_DIM + k4 * 4];
        *(float4*)&sWi[r * XS + k4 * 4] = v;
    }
    // stage x[0]
    for (int i = tid; i < BPC * (IN_DIM / 4); i += 512) {
        int r  = i >> 6;
        int k4 = i & 63;
        float4 v = *(const float4*)&x[(size_t)(b0 + r) * IN_DIM + k4 * 4];
        *(float4*)&sX[r * XS + k4 * 4] = v;
    }
    __syncthreads();
    const unsigned base = s_base;

    const ulonglong2* w2  = (const ulonglong2*)&sW[c * WS] + kh * 64;   // k-half (h)
    const ulonglong2* h2r = (const ulonglong2*)&sH[bl * HS] + kh * 64;
    const ulonglong2* wo2 = (const ulonglong2*)&sWo[oc * WS] + q * 32;  // k-quarter (y)
    const ulonglong2* hy2 = (const ulonglong2*)&sH[yb * HS] + q * 32;
    const ulonglong2* wi2 = (const ulonglong2*)&sWi[c * XS] + kh * 32;  // k-half (xp)
    const ulonglong2* x2  = (const ulonglong2*)&sX[bl * XS] + kh * 32;

    // ---- xp[0] from sX = x[0] ----
    float my_xp = 0.f;
    {
        unsigned long long a01 = 0ull, a23 = 0ull;
        #pragma unroll 8
        for (int k4 = 0; k4 < 32; ++k4) {
            ulonglong2 xv = x2[k4];
            ulonglong2 wv = wi2[k4];
            FMA2(a01, xv.x, wv.x);
            FMA2(a23, xv.y, wv.y);
        }
        float s0, s1, s2, s3;
        asm("mov.b64 {%0, %1}, %2;" : "=f"(s0), "=f"(s1) : "l"(a01));
        asm("mov.b64 {%0, %1}, %2;" : "=f"(s2), "=f"(s3) : "l"(a23));
        float xpp = (s0 + s1) + (s2 + s3);
        if (kh) sP2[inner] = xpp;
        __syncthreads();
        if (!kh) my_xp = xpp + sP2[inner] + bias_c;
        __syncthreads();                          // everyone done reading sX
    }
    // stage x[1]
    for (int i = tid; i < BPC * (IN_DIM / 4); i += 512) {
        int r  = i >> 6;
        int k4 = i & 63;
        float4 v = *(const float4*)&x[(size_t)BATCH * IN_DIM + (size_t)(b0 + r) * IN_DIM + k4 * 4];
        *(float4*)&sX[r * XS + k4 * 4] = v;
    }
    __syncthreads();

    for (int t = 0; t < T_STEPS; ++t) {
        // ---- h[t] partial over this thread's k-half ----
        float part = 0.f;
        if (t > 0) {
            unsigned long long a01 = 0ull, a23 = 0ull;
            #pragma unroll 8
            for (int k4 = 0; k4 < 64; ++k4) {
                ulonglong2 hv = h2r[k4];
                ulonglong2 wv = w2[k4];
                FMA2(a01, hv.x, wv.x);
                FMA2(a23, hv.y, wv.y);
            }
            float s0, s1, s2, s3;
            asm("mov.b64 {%0, %1}, %2;" : "=f"(s0), "=f"(s1) : "l"(a01));
            asm("mov.b64 {%0, %1}, %2;" : "=f"(s2), "=f"(s3) : "l"(a23));
            part = (s0 + s1) + (s2 + s3);
        }
        if (kh) sP[inner] = part;
        __syncthreads();                      // sP visible

        if (!kh) {
            float hn = tanh_fast(my_xp + part + sP[inner]);
            g_rnn[(size_t)t * BH + (size_t)b * HID + colg] = hn;
            if (t == T_STEPS - 1)
                h_out[(size_t)b * HID + colg] = hn;
        }
        __syncthreads();                      // all h[t] stores issued
        if (tid == 0)
            st_rel(&g_flags2[bh][cg], base + (unsigned)t + 1u);  // publish

        // ---- gap work 1: y[t-1] quarter-partial from STABLE sH (= h[t-1]) ----
        float ypart = 0.f;
        if (t > 0) {
            unsigned long long a01 = 0ull, a23 = 0ull;
            #pragma unroll 8
            for (int k4 = 0; k4 < 32; ++k4) {
                ulonglong2 hv = hy2[k4];
                ulonglong2 wv = wo2[k4];
                FMA2(a01, hv.x, wv.x);
                FMA2(a23, hv.y, wv.y);
            }
            float s0, s1, s2, s3;
            asm("mov.b64 {%0, %1}, %2;" : "=f"(s0), "=f"(s1) : "l"(a01));
            asm("mov.b64 {%0, %1}, %2;" : "=f"(s2), "=f"(s3) : "l"(a23));
            ypart = (s0 + s1) + (s2 + s3);
            if (q) sY[(q - 1) * 128 + o] = ypart;
        }

        // ---- gap work 2: xp[t+1] half-partial from sX (= x[t+1]) ----
        float xpp = 0.f;
        if (t + 1 < T_STEPS) {
            unsigned long long a01 = 0ull, a23 = 0ull;
            #pragma unroll 8
            for (int k4 = 0; k4 < 32; ++k4) {
                ulonglong2 xv = x2[k4];
                ulonglong2 wv = wi2[k4];
                FMA2(a01, xv.x, wv.x);
                FMA2(a23, xv.y, wv.y);
            }
            float s0, s1, s2, s3;
            asm("mov.b64 {%0, %1}, %2;" : "=f"(s0), "=f"(s1) : "l"(a01));
            asm("mov.b64 {%0, %1}, %2;" : "=f"(s2), "=f"(s3) : "l"(a23));
            xpp = (s0 + s1) + (s2 + s3);
            if (kh) sP2[inner] = xpp;
        }

        // ---- barrier: wait for whole bh group to publish h[t] ----
        const unsigned target = base + (unsigned)t + 1u;
        if (tid < 32) {
            bool ok;
            do {
                unsigned v = ld_acq(&g_flags2[bh][tid]);
                ok = __all_sync(0xffffffffu, (int)(v - target) >= 0);
            } while (!ok);
        }
        __syncthreads();                      // flags seen; sY/sP2 visible

        if (t > 0 && q == 0)
            y[(size_t)(t - 1) * (BATCH * OUT_DIM) + (size_t)(b0 + yb) * OUT_DIM + ocg]
                = bo + ypart + sY[o] + sY[128 + o] + sY[256 + o];
        if (!kh && t + 1 < T_STEPS)
            my_xp = xpp + sP2[inner] + bias_c;    // xp[t+1] ready

        // ---- stage h[t] into sH; stage x[t+2] into sX ----
        const float* src = &g_rnn[(size_t)t * BH + (size_t)b0 * HID];
        #pragma unroll
        for (int i = tid; i < BPC * (HID / 4); i += 512) {
            int r  = i >> 7;
            int k4 = i & 127;
            float4 v = *(const float4*)&src[(size_t)r * HID + k4 * 4];
            *(float4*)&sH[r * HS + k4 * 4] = v;
        }
        if (t + 2 < T_STEPS) {
            const float* xs = &x[(size_t)(t + 2) * (BATCH * IN_DIM)];
            #pragma unroll
            for (int i = tid; i < BPC * (IN_DIM / 4); i += 512) {
                int r  = i >> 6;
                int k4 = i & 63;
                float4 v = *(const float4*)&xs[(size_t)(b0 + r) * IN_DIM + k4 * 4];
                *(float4*)&sX[r * XS + k4 * 4] = v;
            }
        }
        __syncthreads();                      // sH = h[t], sX = x[t+2] complete
    }

    // ---- epilogue: y[511] from sH = h[511] ----
    {
        unsigned long long a01 = 0ull, a23 = 0ull;
        #pragma unroll 8
        for (int k4 = 0; k4 < 32; ++k4) {
            ulonglong2 hv = hy2[k4];
            ulonglong2 wv = wo2[k4];
            FMA2(a01, hv.x, wv.x);
            FMA2(a23, hv.y, wv.y);
        }
        float s0, s1, s2, s3;
        asm("mov.b64 {%0, %1}, %2;" : "=f"(s0), "=f"(s1) : "l"(a01));
        asm("mov.b64 {%0, %1}, %2;" : "=f"(s2), "=f"(s3) : "l"(a23));
        float ypart = (s0 + s1) + (s2 + s3);
        if (q) sY[(q - 1) * 128 + o] = ypart;
        __syncthreads();
        if (q == 0)
            y[(size_t)(T_STEPS - 1) * (BATCH * OUT_DIM) + (size_t)(b0 + yb) * OUT_DIM + ocg]
                = bo + ypart + sY[o] + sY[128 + o] + sY[256 + o];
    }

    // advance epoch for the next launch (monotonic flags)
    if (bid == 0 && tid == 0)
        *(volatile unsigned*)&g_epoch = base + (unsigned)T_STEPS;
}

// -------------------- launch --------------------
extern "C" void kernel_launch(void* const* d_in, const int* in_sizes, int n_in,
                              void* d_out, int out_size)
{
    const float* x     = (const float*)d_in[0];
    const float* W_ih  = (const float*)d_in[1];
    const float* W_hh  = (const float*)d_in[2];
    const float* b_ih  = (const float*)d_in[3];
    const float* b_hh  = (const float*)d_in[4];
    const float* W_out = (const float*)d_in[5];
    const float* b_out = (const float*)d_in[6];

    float* y = (float*)d_out;                             // [T,B,O]
    float* h = y + (size_t)T_STEPS * BATCH * OUT_DIM;     // [1,B,H]

    // single fully-fused kernel: K1 + scan + K3 in one persistent launch
    cudaFuncSetAttribute(rnn_scan12, cudaFuncAttributeMaxDynamicSharedMemorySize,
                         SMEM_SCAN_BYTES);
    rnn_scan12<<<SCAN_CTAS, 512, SMEM_SCAN_BYTES>>>(
        W_hh, W_ih, b_ih, b_hh, W_out, b_out, x, y, h);
}

// round 16
// speedup vs baseline: 1.2996x; 1.2996x over previous
#include <cuda_runtime.h>
#include <math.h>
#include <stdint.h>

#define T_STEPS 512
#define BATCH   64
#define IN_DIM  256
#define HID     512
#define OUT_DIM 256
#define BH      (BATCH * HID)        // 32768
#define M_ROWS  (T_STEPS * BATCH)    // 32768

// Scratch (allocation-free rule: __device__ globals)
__device__ float g_xp[(size_t)M_ROWS * HID];   // xp = x@W_ih^T + b_ih + b_hh
__device__ float g_rnn[(size_t)M_ROWS * HID];  // h history (exchange medium)

// ---- barrier state: monotonic flags + persistent epoch ----
#define SCAN_CTAS 128
#define NGROUPS   4     // batch groups
__device__ __align__(128) unsigned g_flags2[NGROUPS][32];  // one 128B line per group
__device__ unsigned g_epoch;

__device__ __forceinline__ unsigned ld_acq(const unsigned* p) {
    unsigned v;
    asm volatile("ld.acquire.gpu.u32 %0, [%1];" : "=r"(v) : "l"(p));
    return v;
}
__device__ __forceinline__ void st_rel(unsigned* p, unsigned v) {
    asm volatile("st.release.gpu.u32 [%0], %1;" :: "l"(p), "r"(v));
}

// fast tanh: rel err ~1e-6, clamped (no NaN)
__device__ __forceinline__ float tanh_fast(float x) {
    float xc = fminf(9.0f, fmaxf(-9.0f, x));
    float e  = exp2f(2.885390081777927f * xc);   // e^(2x)
    return __fdividef(e - 1.0f, e + 1.0f);
}

#define FMA2(acc, a, b) asm("fma.rn.f32x2 %0, %1, %2, %0;" : "+l"(acc) : "l"(a), "l"(b))

// -------------------- SGEMM: C[M,N] = A[M,K] @ Bw[N,K]^T + bias --------------------
template<int BM, int BN, int BK, int TM, int TN, int THREADS>
__global__ __launch_bounds__(THREADS)
void sgemm_bt_bias(const float* __restrict__ A,
                   const float* __restrict__ Bw,
                   const float* __restrict__ bias0,
                   const float* __restrict__ bias1,
                   float* __restrict__ C,
                   int M, int N, int K)
{
    __shared__ float As[BK][BM];
    __shared__ float Bs[BK][BN];

    const int tid = threadIdx.x;
    const int tx  = tid % (BN / TN);
    const int ty  = tid / (BN / TN);
    const int m0  = blockIdx.y * BM;
    const int n0  = blockIdx.x * BN;

    float acc[TM][TN];
    #pragma unroll
    for (int i = 0; i < TM; ++i)
        #pragma unroll
        for (int j = 0; j < TN; ++j) acc[i][j] = 0.f;

    for (int k0 = 0; k0 < K; k0 += BK) {
        #pragma unroll
        for (int i = tid; i < (BM * BK) / 4; i += THREADS) {
            int r  = i / (BK / 4);
            int c4 = i % (BK / 4);
            float4 v = *(const float4*)&A[(size_t)(m0 + r) * K + k0 + c4 * 4];
            As[c4 * 4 + 0][r] = v.x;
            As[c4 * 4 + 1][r] = v.y;
            As[c4 * 4 + 2][r] = v.z;
            As[c4 * 4 + 3][r] = v.w;
        }
        #pragma unroll
        for (int i = tid; i < (BN * BK) / 4; i += THREADS) {
            int r  = i / (BK / 4);
            int c4 = i % (BK / 4);
            float4 v = *(const float4*)&Bw[(size_t)(n0 + r) * K + k0 + c4 * 4];
            Bs[c4 * 4 + 0][r] = v.x;
            Bs[c4 * 4 + 1][r] = v.y;
            Bs[c4 * 4 + 2][r] = v.z;
            Bs[c4 * 4 + 3][r] = v.w;
        }
        __syncthreads();

        #pragma unroll
        for (int kk = 0; kk < BK; ++kk) {
            float aR[TM], bR[TN];
            #pragma unroll
            for (int i = 0; i < TM; ++i) aR[i] = As[kk][ty * TM + i];
            #pragma unroll
            for (int j = 0; j < TN; ++j) bR[j] = Bs[kk][tx * TN + j];
            #pragma unroll
            for (int i = 0; i < TM; ++i)
                #pragma unroll
                for (int j = 0; j < TN; ++j)
                    acc[i][j] += aR[i] * bR[j];
        }
        __syncthreads();
    }

    float bj[TN];
    #pragma unroll
    for (int j = 0; j < TN; ++j) {
        int n = n0 + tx * TN + j;
        bj[j] = bias0[n] + (bias1 ? bias1[n] : 0.f);
    }
    #pragma unroll
    for (int i = 0; i < TM; ++i) {
        int m = m0 + ty * TM + i;
        #pragma unroll
        for (int j = 0; j < TN; ++j) {
            int n = n0 + tx * TN + j;
            C[(size_t)m * N + n] = acc[i][j] + bj[j];
        }
    }
}

// -------------------- fused scan + y GEMM (v13: R14 skeleton, 1024 thr) --------
// 128 CTAs = 32 col-groups x 4 batch-groups. CTA: 16 h-cols x 16 batches.
// 1024 threads: each h output = 4 threads (quarter-k), each y output = 8 threads
// (eighth-k, computed inside the barrier window). Partials combined via SMEM.
#define COLS_PER_CTA 16
#define BPC          16
#define OC_CTA       8            // y-cols per col-group (256/32)
#define WS           516
#define HS           520
#define SW_F   (COLS_PER_CTA * WS)   // 8256 floats
#define SWO_F  (OC_CTA * WS)         // 4128
#define SH_F   (BPC * HS)            // 8320
#define SP_F   (3 * 256)             // h partials (kq=1..3)
#define SY_F   (7 * 128)             // y partials (q=1..7)
#define SMEM_SCAN_BYTES ((SW_F + SWO_F + SH_F + SP_F + SY_F) * 4)   // 89472

__global__ __launch_bounds__(1024)
void rnn_scan13(const float* __restrict__ Whh,    // [HID, HID]
                const float* __restrict__ Wout,   // [OUT_DIM, HID]
                const float* __restrict__ b_out,  // [OUT_DIM]
                float* __restrict__ y,            // [T, B, O] (d_out)
                float* __restrict__ h_out)        // [B, HID]  (d_out tail)
{
    extern __shared__ float sm[];
    float* sW  = sm;                // [16][WS]
    float* sWo = sW + SW_F;         // [8][WS]
    float* sH  = sWo + SWO_F;       // [16][HS]  h[t-1] staged
    float* sP  = sH + SH_F;         // [768] h partials (kq 1..3)
    float* sY  = sP + SP_F;         // [896] y partials (q 1..7)
    __shared__ unsigned s_base;

    const int tid = threadIdx.x;
    const int bid = blockIdx.x;
    const int bh  = bid & 3;
    const int cg  = bid >> 2;

    // h mapping: inner = tid&255 (R4 warp shape); kq = tid>>8 = k-quarter (0..3)
    const int inner = tid & 255;
    const int kq    = tid >> 8;
    const int w = inner >> 5, l = inner & 31;
    const int c  = ((w & 1) << 3) + (l & 7);      // 0..15
    const int bl = ((w >> 1) << 2) + (l >> 3);    // 0..15
    const int colg = cg * COLS_PER_CTA + c;
    const int b    = bh * BPC + bl;
    const int b0   = bh * BPC;

    // y mapping: o = tid&127 -> (yb, oc); q = tid>>7 = k-eighth (0..7)
    const int o   = tid & 127;
    const int q   = tid >> 7;
    const int yb  = o >> 3;
    const int oc  = o & 7;
    const int ocg = cg * OC_CTA + oc;
    const float bo = b_out[ocg];

    if (tid == 0) s_base = *(volatile unsigned*)&g_epoch;

    // cache W_hh rows [cg*16, +16) and W_out rows [cg*8, +8)
    for (int i = tid; i < COLS_PER_CTA * (HID / 4); i += 1024) {
        int r  = i >> 7;
        int k4 = i & 127;
        float4 v = *(const float4*)&Whh[(size_t)(cg * COLS_PER_CTA + r) * HID + k4 * 4];
        *(float4*)&sW[r * WS + k4 * 4] = v;
    }
    for (int i = tid; i < OC_CTA * (HID / 4); i += 1024) {
        int r  = i >> 7;
        int k4 = i & 127;
        float4 v = *(const float4*)&Wout[(size_t)(cg * OC_CTA + r) * HID + k4 * 4];
        *(float4*)&sWo[r * WS + k4 * 4] = v;
    }
    __syncthreads();
    const unsigned base = s_base;

    float my_xp = (kq == 0) ? g_xp[(size_t)b * HID + colg] : 0.f;   // t = 0

    const ulonglong2* w2  = (const ulonglong2*)&sW[c * WS] + kq * 32;   // k-quarter
    const ulonglong2* h2r = (const ulonglong2*)&sH[bl * HS] + kq * 32;
    const ulonglong2* wo2 = (const ulonglong2*)&sWo[oc * WS] + q * 16;  // k-eighth
    const ulonglong2* hy2 = (const ulonglong2*)&sH[yb * HS] + q * 16;

    for (int t = 0; t < T_STEPS; ++t) {
        // ---- h[t] partial over this thread's k-quarter ----
        float part = 0.f;
        if (t > 0) {
            unsigned long long a01 = 0ull, a23 = 0ull;
            #pragma unroll 8
            for (int k4 = 0; k4 < 32; ++k4) {
                ulonglong2 hv = h2r[k4];
                ulonglong2 wv = w2[k4];
                FMA2(a01, hv.x, wv.x);
                FMA2(a23, hv.y, wv.y);
            }
            float s0, s1, s2, s3;
            asm("mov.b64 {%0, %1}, %2;" : "=f"(s0), "=f"(s1) : "l"(a01));
            asm("mov.b64 {%0, %1}, %2;" : "=f"(s2), "=f"(s3) : "l"(a23));
            part = (s0 + s1) + (s2 + s3);
        }
        if (kq) sP[(kq - 1) * 256 + inner] = part;
        __syncthreads();                      // sP visible

        if (!kq) {
            float hn = tanh_fast(my_xp + part + sP[inner] + sP[256 + inner] + sP[512 + inner]);
            g_rnn[(size_t)t * BH + (size_t)b * HID + colg] = hn;
            if (t == T_STEPS - 1)
                h_out[(size_t)b * HID + colg] = hn;
        }
        __syncthreads();                      // all h[t] stores issued
        if (tid == 0)
            st_rel(&g_flags2[bh][cg], base + (unsigned)t + 1u);  // publish

        // ---- gap work: y[t-1] eighth-partial from STABLE sH (= h[t-1]) ----
        float ypart = 0.f;
        if (t > 0) {
            unsigned long long a01 = 0ull, a23 = 0ull;
            #pragma unroll 8
            for (int k4 = 0; k4 < 16; ++k4) {
                ulonglong2 hv = hy2[k4];
                ulonglong2 wv = wo2[k4];
                FMA2(a01, hv.x, wv.x);
                FMA2(a23, hv.y, wv.y);
            }
            float s0, s1, s2, s3;
            asm("mov.b64 {%0, %1}, %2;" : "=f"(s0), "=f"(s1) : "l"(a01));
            asm("mov.b64 {%0, %1}, %2;" : "=f"(s2), "=f"(s3) : "l"(a23));
            ypart = (s0 + s1) + (s2 + s3);
            if (q) sY[(q - 1) * 128 + o] = ypart;
        }

        // ---- barrier: wait for whole bh group to publish h[t] ----
        const unsigned target = base + (unsigned)t + 1u;
        if (tid < 32) {
            bool ok;
            do {
                unsigned v = ld_acq(&g_flags2[bh][tid]);
                ok = __all_sync(0xffffffffu, (int)(v - target) >= 0);
            } while (!ok);
        }
        __syncthreads();                      // flags seen; sY visible

        if (t > 0 && q == 0) {
            float acc = bo + ypart;
            #pragma unroll
            for (int p = 0; p < 7; ++p) acc += sY[p * 128 + o];
            y[(size_t)(t - 1) * (BATCH * OUT_DIM) + (size_t)(b0 + yb) * OUT_DIM + ocg] = acc;
        }

        // ---- stage h[t] rows b0..b0+15 into sH; prefetch next xp ----
        const float* src = &g_rnn[(size_t)t * BH + (size_t)b0 * HID];
        #pragma unroll
        for (int i = tid; i < BPC * (HID / 4); i += 1024) {
            int r  = i >> 7;
            int k4 = i & 127;
            float4 v = *(const float4*)&src[(size_t)r * HID + k4 * 4];
            *(float4*)&sH[r * HS + k4 * 4] = v;
        }
        if (!kq && t + 1 < T_STEPS)
            my_xp = g_xp[(size_t)(t + 1) * BH + (size_t)b * HID + colg];
        __syncthreads();                      // sH = h[t] complete
    }

    // ---- epilogue: y[511] from sH = h[511] ----
    {
        unsigned long long a01 = 0ull, a23 = 0ull;
        #pragma unroll 8
        for (int k4 = 0; k4 < 16; ++k4) {
            ulonglong2 hv = hy2[k4];
            ulonglong2 wv = wo2[k4];
            FMA2(a01, hv.x, wv.x);
            FMA2(a23, hv.y, wv.y);
        }
        float s0, s1, s2, s3;
        asm("mov.b64 {%0, %1}, %2;" : "=f"(s0), "=f"(s1) : "l"(a01));
        asm("mov.b64 {%0, %1}, %2;" : "=f"(s2), "=f"(s3) : "l"(a23));
        float ypart = (s0 + s1) + (s2 + s3);
        if (q) sY[(q - 1) * 128 + o] = ypart;
        __syncthreads();
        if (q == 0) {
            float acc = bo + ypart;
            #pragma unroll
            for (int p = 0; p < 7; ++p) acc += sY[p * 128 + o];
            y[(size_t)(T_STEPS - 1) * (BATCH * OUT_DIM) + (size_t)(b0 + yb) * OUT_DIM + ocg] = acc;
        }
    }

    // advance epoch for the next launch (monotonic flags)
    if (bid == 0 && tid == 0)
        *(volatile unsigned*)&g_epoch = base + (unsigned)T_STEPS;
}

__global__ void dummy_k() {}

// -------------------- launch --------------------
extern "C" void kernel_launch(void* const* d_in, const int* in_sizes, int n_in,
                              void* d_out, int out_size)
{
    const float* x     = (const float*)d_in[0];
    const float* W_ih  = (const float*)d_in[1];
    const float* W_hh  = (const float*)d_in[2];
    const float* b_ih  = (const float*)d_in[3];
    const float* b_hh  = (const float*)d_in[4];
    const float* W_out = (const float*)d_in[5];
    const float* b_out = (const float*)d_in[6];

    float* y = (float*)d_out;                             // [T,B,O]
    float* h = y + (size_t)T_STEPS * BATCH * OUT_DIM;     // [1,B,H]

    float* xp = nullptr;
    cudaGetSymbolAddress((void**)&xp, g_xp);

    // K1: xp = x @ W_ih^T + b_ih + b_hh    (M=32768, N=512, K=256)
    {
        dim3 grid(HID / 64, M_ROWS / 128);
        sgemm_bt_bias<128, 64, 16, 8, 4, 256><<<grid, 256>>>(
            x, W_ih, b_ih, b_hh, xp, M_ROWS, HID, IN_DIM);
    }

    // two dummies so the fused scan sits at global launch #6 for ncu (-s 5 -c 1)
    dummy_k<<<1, 32>>>();
    dummy_k<<<1, 32>>>();

    // K2: fused recurrence + output GEMM; writes y + h_last
    cudaFuncSetAttribute(rnn_scan13, cudaFuncAttributeMaxDynamicSharedMemorySize,
                         SMEM_SCAN_BYTES);
    rnn_scan13<<<SCAN_CTAS, 1024, SMEM_SCAN_BYTES>>>(W_hh, W_out, b_out, y, h);
}

// round 17
// speedup vs baseline: 2.0223x; 1.5561x over previous
#include <cuda_runtime.h>
#include <cuda_fp16.h>
#include <math.h>
#include <stdint.h>

#define T_STEPS 512
#define BATCH   64
#define IN_DIM  256
#define HID     512
#define OUT_DIM 256
#define BH      (BATCH * HID)        // 32768
#define M_ROWS  (T_STEPS * BATCH)    // 32768

// Scratch (allocation-free rule: __device__ globals)
__device__ float  g_xp[(size_t)M_ROWS * HID];      // xp = x@W_ih^T + b_ih + b_hh (fp32)
__device__ __half g_rnn_h[(size_t)M_ROWS * HID];   // h history in fp16 (exchange medium)

// ---- barrier state: monotonic flags + persistent epoch ----
#define SCAN_CTAS 128
#define NGROUPS   4
__device__ __align__(128) unsigned g_flags2[NGROUPS][32];
__device__ unsigned g_epoch;

__device__ __forceinline__ unsigned ld_acq(const unsigned* p) {
    unsigned v;
    asm volatile("ld.acquire.gpu.u32 %0, [%1];" : "=r"(v) : "l"(p));
    return v;
}
__device__ __forceinline__ void st_rel(unsigned* p, unsigned v) {
    asm volatile("st.release.gpu.u32 [%0], %1;" :: "l"(p), "r"(v));
}

__device__ __forceinline__ float tanh_fast(float x) {
    float xc = fminf(9.0f, fmaxf(-9.0f, x));
    float e  = exp2f(2.885390081777927f * xc);
    return __fdividef(e - 1.0f, e + 1.0f);
}

__device__ __forceinline__ uint32_t smem_u32(const void* p) {
    uint32_t a;
    asm("{ .reg .u64 t; cvta.to.shared.u64 t, %1; cvt.u32.u64 %0, t; }"
        : "=r"(a) : "l"(p));
    return a;
}

#define LDSM_X4(r0, r1, r2, r3, addr) \
    asm volatile("ldmatrix.sync.aligned.m8n8.x4.shared.b16 {%0,%1,%2,%3}, [%4];" \
                 : "=r"(r0), "=r"(r1), "=r"(r2), "=r"(r3) : "r"(addr))

#define MMA_161616(c, a, b0, b1) \
    asm volatile("mma.sync.aligned.m16n8k16.row.col.f32.f16.f16.f32 " \
                 "{%0,%1,%2,%3},{%4,%5,%6,%7},{%8,%9},{%0,%1,%2,%3};" \
                 : "+f"((c)[0]), "+f"((c)[1]), "+f"((c)[2]), "+f"((c)[3]) \
                 : "r"((a)[0]), "r"((a)[1]), "r"((a)[2]), "r"((a)[3]), \
                   "r"(b0), "r"(b1))

// -------------------- SGEMM (K1, fp32, unchanged) --------------------
template<int BM, int BN, int BK, int TM, int TN, int THREADS>
__global__ __launch_bounds__(THREADS)
void sgemm_bt_bias(const float* __restrict__ A,
                   const float* __restrict__ Bw,
                   const float* __restrict__ bias0,
                   const float* __restrict__ bias1,
                   float* __restrict__ C,
                   int M, int N, int K)
{
    __shared__ float As[BK][BM];
    __shared__ float Bs[BK][BN];

    const int tid = threadIdx.x;
    const int tx  = tid % (BN / TN);
    const int ty  = tid / (BN / TN);
    const int m0  = blockIdx.y * BM;
    const int n0  = blockIdx.x * BN;

    float acc[TM][TN];
    #pragma unroll
    for (int i = 0; i < TM; ++i)
        #pragma unroll
        for (int j = 0; j < TN; ++j) acc[i][j] = 0.f;

    for (int k0 = 0; k0 < K; k0 += BK) {
        #pragma unroll
        for (int i = tid; i < (BM * BK) / 4; i += THREADS) {
            int r = i / (BK / 4), c4 = i % (BK / 4);
            float4 v = *(const float4*)&A[(size_t)(m0 + r) * K + k0 + c4 * 4];
            As[c4 * 4 + 0][r] = v.x; As[c4 * 4 + 1][r] = v.y;
            As[c4 * 4 + 2][r] = v.z; As[c4 * 4 + 3][r] = v.w;
        }
        #pragma unroll
        for (int i = tid; i < (BN * BK) / 4; i += THREADS) {
            int r = i / (BK / 4), c4 = i % (BK / 4);
            float4 v = *(const float4*)&Bw[(size_t)(n0 + r) * K + k0 + c4 * 4];
            Bs[c4 * 4 + 0][r] = v.x; Bs[c4 * 4 + 1][r] = v.y;
            Bs[c4 * 4 + 2][r] = v.z; Bs[c4 * 4 + 3][r] = v.w;
        }
        __syncthreads();
        #pragma unroll
        for (int kk = 0; kk < BK; ++kk) {
            float aR[TM], bR[TN];
            #pragma unroll
            for (int i = 0; i < TM; ++i) aR[i] = As[kk][ty * TM + i];
            #pragma unroll
            for (int j = 0; j < TN; ++j) bR[j] = Bs[kk][tx * TN + j];
            #pragma unroll
            for (int i = 0; i < TM; ++i)
                #pragma unroll
                for (int j = 0; j < TN; ++j) acc[i][j] += aR[i] * bR[j];
        }
        __syncthreads();
    }
    float bj[TN];
    #pragma unroll
    for (int j = 0; j < TN; ++j) {
        int n = n0 + tx * TN + j;
        bj[j] = bias0[n] + (bias1 ? bias1[n] : 0.f);
    }
    #pragma unroll
    for (int i = 0; i < TM; ++i) {
        int m = m0 + ty * TM + i;
        #pragma unroll
        for (int j = 0; j < TN; ++j)
            C[(size_t)m * N + (n0 + tx * TN + j)] = acc[i][j] + bj[j];
    }
}

// -------------------- fused scan + y GEMM (v14: fp16 tensor cores) --------------
// 128 CTAs = 32 col-groups x 4 batch-groups. CTA: m=16 batches, n=16 h-cols,
// 8 y-cols, k=512. 1024 threads = 32 warps: warps 0-15 h-mma (k-slice 32 each),
// warps 16-31 y-mma (k-slice 32 each), concurrent, both reading stable sH(h[t-1]).
// fp16 operands, fp32 accumulate; k-partials combined via SMEM (proven sP path).
#define COLS_PER_CTA 16
#define BPC          16
#define OC_CTA       8
#define HSTR_H       520          // half stride: rows land 4 banks apart (conflict-free)
#define SPH_STR      264          // h partials row stride (floats)
#define SPY_STR      136          // y partials row stride (floats)
#define SPH_OFF      0                                 // [16][264] f32
#define SPY_OFF      (16 * SPH_STR)                    // [16][136] f32
#define FP32_F       (SPY_OFF + 16 * SPY_STR)          // total f32 words
#define SWH_OFF      0                                 // halves, after fp32 region
#define SWO_OFF      (16 * HSTR_H)                     // [8][520] halves
#define SH_OFF       (SWO_OFF + 8 * HSTR_H)            // [16][520] halves
#define HALF_CNT     (SH_OFF + 16 * HSTR_H)
#define SMEM_SCAN_BYTES (FP32_F * 4 + HALF_CNT * 2)    // ~ 67.2 KB

__global__ __launch_bounds__(1024)
void rnn_scan14(const float* __restrict__ Whh,    // [HID, HID]
                const float* __restrict__ Wout,   // [OUT_DIM, HID]
                const float* __restrict__ b_out,  // [OUT_DIM]
                float* __restrict__ y,            // [T, B, O] (d_out)
                float* __restrict__ h_out)        // [B, HID]  (d_out tail)
{
    extern __shared__ float smf[];
    float*  sPh = smf + SPH_OFF;
    float*  sPy = smf + SPY_OFF;
    __half* smh = (__half*)(smf + FP32_F);
    __half* sW  = smh + SWH_OFF;   // W_hh slice [16][520]
    __half* sWo = smh + SWO_OFF;   // W_out slice [8][520]
    __half* sH  = smh + SH_OFF;    // h[t-1] [16][520]
    __shared__ unsigned s_base;

    const int tid = threadIdx.x;
    const int bid = blockIdx.x;
    const int bh  = bid & 3;
    const int cg  = bid >> 2;
    const int wid = tid >> 5;
    const int ln  = tid & 31;
    const int b0  = bh * BPC;

    if (tid == 0) s_base = *(volatile unsigned*)&g_epoch;

    // prologue: convert W slices to fp16 in SMEM
    for (int i = tid; i < COLS_PER_CTA * HID; i += 1024) {
        int r = i >> 9, k = i & (HID - 1);
        sW[r * HSTR_H + k] = __float2half(Whh[(size_t)(cg * COLS_PER_CTA + r) * HID + k]);
    }
    for (int i = tid; i < OC_CTA * HID; i += 1024) {
        int r = i >> 9, k = i & (HID - 1);
        sWo[r * HSTR_H + k] = __float2half(Wout[(size_t)(cg * OC_CTA + r) * HID + k]);
    }
    __syncthreads();
    const unsigned base = s_base;

    const uint32_t sH_a  = smem_u32(sH);
    const uint32_t sW_a  = smem_u32(sW);
    const uint32_t sWo_a = smem_u32(sWo);

    // h-output mapping (threads 0-255): o -> (bl, c)
    const int o_h   = tid & 255;
    const int bl_h  = o_h >> 4;
    const int c_h   = o_h & 15;
    const int colg  = cg * COLS_PER_CTA + c_h;
    const int b_h   = b0 + bl_h;
    // y-output mapping (threads 256-383): oy -> (yb, oc)
    const int oy    = tid - 256;              // valid when 0<=oy<128
    const int yb    = (oy >> 3) & 15;
    const int oc    = oy & 7;
    const int ocg   = cg * OC_CTA + oc;
    const float bo  = b_out[cg * OC_CTA + (tid & 7)];  // only used by y threads (oc == tid&7 there)

    float my_xp = (tid < 256) ? g_xp[(size_t)b_h * HID + colg] : 0.f;

    // per-warp mma setup
    const int kslice = (wid & 15) * 32;      // k0 for this warp
    // A lane address: row = ln&15, k = kslice + (ln>>4)*8
    const uint32_t aAddrBase = sH_a + (uint32_t)(((ln & 15) * HSTR_H + kslice + ((ln >> 4) << 3)) * 2);
    // B lane address pieces: row = n0 + (ln&7), k = kslice + (ln>>3)*8
    const uint32_t bRowOff = (uint32_t)((ln & 7) * HSTR_H * 2);
    const uint32_t bKOff   = (uint32_t)((kslice + ((ln >> 3) << 3)) * 2);

    for (int t = 0; t < T_STEPS; ++t) {
        // ---- phase A: mma partials (warps 0-15: h; warps 16-31: y[t-1]) ----
        if (t > 0) {
            uint32_t aLo[4], aHi[4];
            LDSM_X4(aLo[0], aLo[1], aLo[2], aLo[3], aAddrBase);
            LDSM_X4(aHi[0], aHi[1], aHi[2], aHi[3], aAddrBase + 32);  // k +16 halves
            if (wid < 16) {
                float c0[4] = {0,0,0,0}, c1[4] = {0,0,0,0};
                uint32_t bt[4];
                LDSM_X4(bt[0], bt[1], bt[2], bt[3], sW_a + bRowOff + bKOff);            // n0-7
                MMA_161616(c0, aLo, bt[0], bt[1]);
                MMA_161616(c0, aHi, bt[2], bt[3]);
                LDSM_X4(bt[0], bt[1], bt[2], bt[3], sW_a + bRowOff + (uint32_t)(8 * HSTR_H * 2) + bKOff); // n8-15
                MMA_161616(c1, aLo, bt[0], bt[1]);
                MMA_161616(c1, aHi, bt[2], bt[3]);
                // store partials: lane ln: r=ln>>2, tq=ln&3
                int r = ln >> 2, tq = ln & 3;
                float* dst = &sPh[(wid & 15) * SPH_STR];
                *(float2*)&dst[r * 16 + tq * 2]        = make_float2(c0[0], c0[1]);
                *(float2*)&dst[(r + 8) * 16 + tq * 2]  = make_float2(c0[2], c0[3]);
                *(float2*)&dst[r * 16 + 8 + tq * 2]       = make_float2(c1[0], c1[1]);
                *(float2*)&dst[(r + 8) * 16 + 8 + tq * 2] = make_float2(c1[2], c1[3]);
            } else {
                float c0[4] = {0,0,0,0};
                uint32_t bt[4];
                LDSM_X4(bt[0], bt[1], bt[2], bt[3], sWo_a + bRowOff + bKOff);           // n0-7
                MMA_161616(c0, aLo, bt[0], bt[1]);
                MMA_161616(c0, aHi, bt[2], bt[3]);
                int r = ln >> 2, tq = ln & 3;
                float* dst = &sPy[(wid & 15) * SPY_STR];
                *(float2*)&dst[r * 8 + tq * 2]        = make_float2(c0[0], c0[1]);
                *(float2*)&dst[(r + 8) * 8 + tq * 2]  = make_float2(c0[2], c0[3]);
            }
        }
        __syncthreads();   // syncA: partials visible

        // ---- phase B: h reduce + tanh + publish (threads 0-255) ----
        if (tid < 256) {
            float part = 0.f;
            if (t > 0) {
                #pragma unroll
                for (int j = 0; j < 16; ++j) part += sPh[j * SPH_STR + o_h];
            }
            float hn = tanh_fast(my_xp + part);
            g_rnn_h[(size_t)t * BH + (size_t)b_h * HID + colg] = __float2half(hn);
            if (t == T_STEPS - 1)
                h_out[(size_t)b_h * HID + colg] = hn;
        }
        __syncthreads();   // syncB: all h stores issued
        if (tid == 0)
            st_rel(&g_flags2[bh][cg], base + (unsigned)t + 1u);

        // ---- gap: y[t-1] reduce + store (threads 256-383) ----
        if (t > 0 && tid >= 256 && tid < 384) {
            float acc = bo;
            #pragma unroll
            for (int j = 0; j < 16; ++j) acc += sPy[j * SPY_STR + oy];
            y[(size_t)(t - 1) * (BATCH * OUT_DIM) + (size_t)(b0 + yb) * OUT_DIM + ocg] = acc;
        }

        // ---- barrier: wait for bh group ----
        const unsigned target = base + (unsigned)t + 1u;
        if (tid < 32) {
            bool ok;
            do {
                unsigned v = ld_acq(&g_flags2[bh][tid]);
                ok = __all_sync(0xffffffffu, (int)(v - target) >= 0);
            } while (!ok);
        }
        __syncthreads();   // syncC

        // ---- stage h[t] (fp16, 16 KB) into sH; prefetch next xp ----
        {
            int r = tid >> 6, seg = tid & 63;
            const uint4* src = (const uint4*)&g_rnn_h[(size_t)t * BH + (size_t)(b0 + r) * HID];
            *(uint4*)&sH[r * HSTR_H + seg * 8] = src[seg];
        }
        if (tid < 256 && t + 1 < T_STEPS)
            my_xp = g_xp[(size_t)(t + 1) * BH + (size_t)b_h * HID + colg];
        __syncthreads();   // syncD: sH = h[t]
    }

    // ---- epilogue: y[511] from sH = h[511] ----
    {
        if (wid >= 16) {
            uint32_t aLo[4], aHi[4], bt[4];
            float c0[4] = {0,0,0,0};
            LDSM_X4(aLo[0], aLo[1], aLo[2], aLo[3], aAddrBase);
            LDSM_X4(aHi[0], aHi[1], aHi[2], aHi[3], aAddrBase + 32);
            LDSM_X4(bt[0], bt[1], bt[2], bt[3], sWo_a + bRowOff + bKOff);
            MMA_161616(c0, aLo, bt[0], bt[1]);
            MMA_161616(c0, aHi, bt[2], bt[3]);
            int r = ln >> 2, tq = ln & 3;
            float* dst = &sPy[(wid & 15) * SPY_STR];
            *(float2*)&dst[r * 8 + tq * 2]        = make_float2(c0[0], c0[1]);
            *(float2*)&dst[(r + 8) * 8 + tq * 2]  = make_float2(c0[2], c0[3]);
        }
        __syncthreads();
        if (tid >= 256 && tid < 384) {
            float acc = bo;
            #pragma unroll
            for (int j = 0; j < 16; ++j) acc += sPy[j * SPY_STR + oy];
            y[(size_t)(T_STEPS - 1) * (BATCH * OUT_DIM) + (size_t)(b0 + yb) * OUT_DIM + ocg] = acc;
        }
    }

    if (bid == 0 && tid == 0)
        *(volatile unsigned*)&g_epoch = base + (unsigned)T_STEPS;
}

__global__ void dummy_k() {}

// -------------------- launch --------------------
extern "C" void kernel_launch(void* const* d_in, const int* in_sizes, int n_in,
                              void* d_out, int out_size)
{
    const float* x     = (const float*)d_in[0];
    const float* W_ih  = (const float*)d_in[1];
    const float* W_hh  = (const float*)d_in[2];
    const float* b_ih  = (const float*)d_in[3];
    const float* b_hh  = (const float*)d_in[4];
    const float* W_out = (const float*)d_in[5];
    const float* b_out = (const float*)d_in[6];

    float* y = (float*)d_out;                             // [T,B,O]
    float* h = y + (size_t)T_STEPS * BATCH * OUT_DIM;     // [1,B,H]

    float* xp = nullptr;
    cudaGetSymbolAddress((void**)&xp, g_xp);

    // K1: xp = x @ W_ih^T + b_ih + b_hh    (fp32, M=32768, N=512, K=256)
    {
        dim3 grid(HID / 64, M_ROWS / 128);
        sgemm_bt_bias<128, 64, 16, 8, 4, 256><<<grid, 256>>>(
            x, W_ih, b_ih, b_hh, xp, M_ROWS, HID, IN_DIM);
    }

    // two dummies so the fused scan sits at global launch #6 for ncu (-s 5 -c 1)
    dummy_k<<<1, 32>>>();
    dummy_k<<<1, 32>>>();

    // K2: fp16 tensor-core recurrence + output GEMM; writes y + h_last
    cudaFuncSetAttribute(rnn_scan14, cudaFuncAttributeMaxDynamicSharedMemorySize,
                         SMEM_SCAN_BYTES);
    rnn_scan14<<<SCAN_CTAS, 1024, SMEM_SCAN_BYTES>>>(W_hh, W_out, b_out, y, h);
}